// round 11
// baseline (speedup 1.0000x reference)
#include <cuda_runtime.h>

// Problem constants
#define B_  2
#define N_  2048
#define D_  1024
#define H_  16
#define DH  64
#define M_  (B_ * N_)   // 4096 rows

// Scratch (device globals — no allocation allowed)
__device__ float g_Q[M_ * D_];
__device__ float g_K[M_ * D_];
__device__ float g_V[M_ * D_];
__device__ float g_C[M_ * D_];

// ---------------------------------------------------------------------------
// Packed f32x2 helpers (Blackwell FFMA2 — 2 FMAs per fma-pipe instruction)
// ---------------------------------------------------------------------------
typedef unsigned long long u64;

__device__ __forceinline__ u64 pack2(float x, float y) {
    u64 r; asm("mov.b64 %0, {%1,%2};" : "=l"(r) : "f"(x), "f"(y)); return r;
}
__device__ __forceinline__ float2 unpack2(u64 v) {
    float2 r; asm("mov.b64 {%0,%1}, %2;" : "=f"(r.x), "=f"(r.y) : "l"(v)); return r;
}
__device__ __forceinline__ u64 ffma2(u64 a, u64 b, u64 c) {
    u64 d; asm("fma.rn.f32x2 %0, %1, %2, %3;" : "=l"(d) : "l"(a), "l"(b), "l"(c)); return d;
}
__device__ __forceinline__ u64 fmul2(u64 a, u64 b) {
    u64 d; asm("mul.rn.f32x2 %0, %1, %2;" : "=l"(d) : "l"(a), "l"(b)); return d;
}
__device__ __forceinline__ u64 swap2(u64 v) {   // {lo,hi} -> {hi,lo}
    u64 r;
    asm("{\n\t.reg .b32 lo, hi;\n\t"
        "mov.b64 {lo, hi}, %1;\n\t"
        "mov.b64 %0, {hi, lo};\n\t}"
        : "=l"(r) : "l"(v));
    return r;
}

// ---------------------------------------------------------------------------
// NT SGEMM tile, FFMA2 diagonal/anti-diagonal microkernel:
//   C[m][n] = sum_k A[m][k] * W[n][k] (+ bias[n])
// BM=BN=128, BK=8, 256 threads, 8x8 per thread as 4x4 PAIR blocks.
// For a-pair {a0,a1} and w-pair {w0,w1}:
//   accD += {a0,a1}*{w0,w1}  -> diag   (a0w0, a1w1)
//   accA += {a0,a1}*{w1,w0}  -> anti   (a0w1, a1w0)
// Operands come straight from 4 LDS.128 per k-step (no duplicated smem).
// ---------------------------------------------------------------------------
__device__ __forceinline__ void gemm_tile(const float* __restrict__ A,
                                          const float* __restrict__ W,
                                          float* __restrict__ C,
                                          const float* __restrict__ bias)
{
    __shared__ float As[8][128];
    __shared__ float Ws[8][128];

    const int tid = threadIdx.x;          // 0..255
    const int tx  = tid & 15;             // 0..15 (N direction)
    const int ty  = tid >> 4;             // 0..15 (M direction)
    const int mbase = blockIdx.y * 128;
    const int nbase = blockIdx.x * 128;

    // Global-load mapping: each thread loads one float4 per tile per matrix.
    const int lr = tid >> 1;              // row within 128-row tile
    const int lc = (tid & 1) * 4;         // 0 or 4 within the 8-wide K slab
    const float* Ap = A + (size_t)(mbase + lr) * D_ + lc;
    const float* Wp = W + (size_t)(nbase + lr) * D_ + lc;

    u64 accD[4][4], accA[4][4];
    #pragma unroll
    for (int i = 0; i < 4; i++)
        #pragma unroll
        for (int j = 0; j < 4; j++) { accD[i][j] = 0ull; accA[i][j] = 0ull; }

    float4 av = *(const float4*)(Ap);
    float4 wv = *(const float4*)(Wp);

    for (int kb = 0; kb < D_; kb += 8) {
        // store current slab (transposed: [k][row])
        As[lc + 0][lr] = av.x; As[lc + 1][lr] = av.y;
        As[lc + 2][lr] = av.z; As[lc + 3][lr] = av.w;
        Ws[lc + 0][lr] = wv.x; Ws[lc + 1][lr] = wv.y;
        Ws[lc + 2][lr] = wv.z; Ws[lc + 3][lr] = wv.w;
        __syncthreads();

        // prefetch next slab while computing
        if (kb + 8 < D_) {
            av = *(const float4*)(Ap + kb + 8);
            wv = *(const float4*)(Wp + kb + 8);
        }

        #pragma unroll
        for (int k = 0; k < 8; k++) {
            ulonglong2 aA = *(const ulonglong2*)&As[k][ty * 8];      // {a0,a1},{a2,a3}
            ulonglong2 aB = *(const ulonglong2*)&As[k][ty * 8 + 4];  // {a4,a5},{a6,a7}
            ulonglong2 wA = *(const ulonglong2*)&Ws[k][tx * 8];
            ulonglong2 wB = *(const ulonglong2*)&Ws[k][tx * 8 + 4];
            u64 a2[4] = { aA.x, aA.y, aB.x, aB.y };
            u64 w2[4] = { wA.x, wA.y, wB.x, wB.y };
            u64 ws[4];
            #pragma unroll
            for (int j = 0; j < 4; j++) ws[j] = swap2(w2[j]);

            #pragma unroll
            for (int i = 0; i < 4; i++)
                #pragma unroll
                for (int j = 0; j < 4; j++) {
                    accD[i][j] = ffma2(a2[i], w2[j], accD[i][j]);
                    accA[i][j] = ffma2(a2[i], ws[j], accA[i][j]);
                }
        }
        __syncthreads();
    }

    // Epilogue: unscramble diag/anti pairs into rows, add bias, store float4.
    #pragma unroll
    for (int ip = 0; ip < 4; ip++) {
        const size_t r0 = (size_t)(mbase + ty * 8 + 2 * ip) * D_;
        const size_t r1 = r0 + D_;
        #pragma unroll
        for (int jh = 0; jh < 2; jh++) {               // two float4 per row
            const int c = nbase + tx * 8 + jh * 4;
            float2 d0 = unpack2(accD[ip][2 * jh]);     // cols c, c+1 (diag)
            float2 x0 = unpack2(accA[ip][2 * jh]);     // cols c+1, c (anti)
            float2 d1 = unpack2(accD[ip][2 * jh + 1]); // cols c+2, c+3
            float2 x1 = unpack2(accA[ip][2 * jh + 1]);
            float4 row0 = make_float4(d0.x, x0.x, d1.x, x1.x);
            float4 row1 = make_float4(x0.y, d0.y, x1.y, d1.y);
            if (bias) {
                float4 bb = *(const float4*)(bias + c);
                row0.x += bb.x; row0.y += bb.y; row0.z += bb.z; row0.w += bb.w;
                row1.x += bb.x; row1.y += bb.y; row1.z += bb.z; row1.w += bb.w;
            }
            *(float4*)(C + r0 + c) = row0;
            *(float4*)(C + r1 + c) = row1;
        }
    }
}

// Fused QKV projection: blockIdx.z selects which weight/output (x tiles L2-shared).
__global__ void __launch_bounds__(256, 2) qkv_kernel(const float* __restrict__ x,
                                                     const float* __restrict__ Wq,
                                                     const float* __restrict__ Wk,
                                                     const float* __restrict__ Wv)
{
    const float* W;
    float* O;
    if (blockIdx.z == 0)      { W = Wq; O = g_Q; }
    else if (blockIdx.z == 1) { W = Wk; O = g_K; }
    else                      { W = Wv; O = g_V; }
    gemm_tile(x, W, O, nullptr);
}

// Output projection: out = ctx @ Wo^T + bo
__global__ void __launch_bounds__(256, 2) outproj_kernel(const float* __restrict__ Wo,
                                                         const float* __restrict__ bo,
                                                         float* __restrict__ out)
{
    gemm_tile(g_C, Wo, out, bo);
}

// ---------------------------------------------------------------------------
// Flash attention (fp32, FFMA2), double-buffered 16-row KV tiles.
// Grid: (N_/128, B_*H_). Block: 128 threads; each thread owns ONE query row:
//   q[64] and o[64] live in registers as 32 packed f32x2 each.
// ---------------------------------------------------------------------------
__global__ void __launch_bounds__(128) flash_kernel()
{
    __shared__ float Ks[2][16][64];
    __shared__ float Vs[2][16][64];

    const int bh = blockIdx.y;
    const int b  = bh >> 4;
    const int h  = bh & 15;
    const int n  = blockIdx.x * 128 + threadIdx.x;     // query row (always < 2048)
    const size_t row = (size_t)(b * N_ + n) * D_ + h * DH;

    // Load + pre-scale q into packed registers
    u64 q2[32];
    {
        const float sc = 0.125f;  // dh^-0.5 = 64^-0.5
        #pragma unroll
        for (int d4 = 0; d4 < 16; d4++) {
            float4 t = *(const float4*)(g_Q + row + d4 * 4);
            q2[2 * d4]     = pack2(t.x * sc, t.y * sc);
            q2[2 * d4 + 1] = pack2(t.z * sc, t.w * sc);
        }
    }

    u64 o2[32];
    #pragma unroll
    for (int i = 0; i < 32; i++) o2[i] = 0ull;   // bit pattern of (0.f, 0.f)
    float m = -1e30f;
    float l = 0.0f;

    const size_t kvbase = (size_t)b * N_ * D_ + h * DH;

    // Per-thread staging map: 2 float4 of K + 2 float4 of V per 16x64 tile.
    const int f0  = threadIdx.x;
    const int f1  = threadIdx.x + 128;
    const int jr0 = f0 >> 4, c40 = (f0 & 15) * 4;
    const int jr1 = f1 >> 4, c41 = (f1 & 15) * 4;
    const size_t off0 = (size_t)jr0 * D_ + c40;
    const size_t off1 = (size_t)jr1 * D_ + c41;

    float4 kr0, kr1, vr0, vr1;

    // Prologue: tile 0 into buffer 0.
    kr0 = *(const float4*)(g_K + kvbase + off0);
    kr1 = *(const float4*)(g_K + kvbase + off1);
    vr0 = *(const float4*)(g_V + kvbase + off0);
    vr1 = *(const float4*)(g_V + kvbase + off1);
    *(float4*)&Ks[0][jr0][c40] = kr0;
    *(float4*)&Ks[0][jr1][c41] = kr1;
    *(float4*)&Vs[0][jr0][c40] = vr0;
    *(float4*)&Vs[0][jr1][c41] = vr1;
    __syncthreads();

    const int T = N_ / 16;   // 128 tiles
    for (int t = 0; t < T; t++) {
        const int cur = t & 1;

        // Issue next tile's global loads; latency overlaps the compute below.
        if (t + 1 < T) {
            const size_t g = kvbase + (size_t)(t + 1) * 16 * D_;
            kr0 = *(const float4*)(g_K + g + off0);
            kr1 = *(const float4*)(g_K + g + off1);
            vr0 = *(const float4*)(g_V + g + off0);
            vr1 = *(const float4*)(g_V + g + off1);
        }

        // S = q . K_j (packed FFMA2, 4 independent accumulator chains)
        float s[16];
        float tmax = -1e30f;
        #pragma unroll
        for (int j = 0; j < 16; j++) {
            const ulonglong2* kp = (const ulonglong2*)&Ks[cur][j][0];  // LDS.128
            u64 a0 = 0ull, a1 = 0ull, a2 = 0ull, a3 = 0ull;
            #pragma unroll
            for (int e = 0; e < 16; e += 2) {
                ulonglong2 ka = kp[e];
                ulonglong2 kb = kp[e + 1];
                a0 = ffma2(q2[2 * e + 0], ka.x, a0);
                a1 = ffma2(q2[2 * e + 1], ka.y, a1);
                a2 = ffma2(q2[2 * e + 2], kb.x, a2);
                a3 = ffma2(q2[2 * e + 3], kb.y, a3);
            }
            float2 t0 = unpack2(a0), t1 = unpack2(a1);
            float2 t2 = unpack2(a2), t3 = unpack2(a3);
            s[j] = ((t0.x + t0.y) + (t1.x + t1.y)) + ((t2.x + t2.y) + (t3.x + t3.y));
            tmax = fmaxf(tmax, s[j]);
        }

        // Online softmax update
        const float mnew = fmaxf(m, tmax);
        const float corr = __expf(m - mnew);   // first iter: exp(-huge) = 0
        m = mnew;
        float ps = 0.0f;
        #pragma unroll
        for (int j = 0; j < 16; j++) { s[j] = __expf(s[j] - mnew); ps += s[j]; }
        l = l * corr + ps;

        const u64 c2 = pack2(corr, corr);
        #pragma unroll
        for (int i = 0; i < 32; i++) o2[i] = fmul2(o2[i], c2);

        // O += P . V (packed FFMA2)
        #pragma unroll
        for (int j = 0; j < 16; j++) {
            const u64 p2 = pack2(s[j], s[j]);
            const ulonglong2* vp = (const ulonglong2*)&Vs[cur][j][0];
            #pragma unroll
            for (int e = 0; e < 16; e++) {
                ulonglong2 vv = vp[e];
                o2[2 * e]     = ffma2(p2, vv.x, o2[2 * e]);
                o2[2 * e + 1] = ffma2(p2, vv.y, o2[2 * e + 1]);
            }
        }

        // Store prefetched tile into the other buffer; barrier covers both
        // "tile t fully consumed" and "tile t+1 visible".
        if (t + 1 < T) {
            const int nxt = 1 - cur;
            *(float4*)&Ks[nxt][jr0][c40] = kr0;
            *(float4*)&Ks[nxt][jr1][c41] = kr1;
            *(float4*)&Vs[nxt][jr0][c40] = vr0;
            *(float4*)&Vs[nxt][jr1][c41] = vr1;
        }
        __syncthreads();
    }

    // Normalize and write context (same [row, h*64 + d] layout as Q)
    const float inv = 1.0f / l;
    const u64 i2 = pack2(inv, inv);
    #pragma unroll
    for (int e = 0; e < 16; e++) {
        ulonglong2 w;
        w.x = fmul2(o2[2 * e],     i2);
        w.y = fmul2(o2[2 * e + 1], i2);
        *(ulonglong2*)(g_C + row + e * 4) = w;
    }
}

// ---------------------------------------------------------------------------
// Launch
// ---------------------------------------------------------------------------
extern "C" void kernel_launch(void* const* d_in, const int* in_sizes, int n_in,
                              void* d_out, int out_size)
{
    (void)in_sizes; (void)n_in; (void)out_size;
    const float* x  = (const float*)d_in[0];
    const float* Wq = (const float*)d_in[1];
    const float* Wk = (const float*)d_in[2];
    const float* Wv = (const float*)d_in[3];
    const float* Wo = (const float*)d_in[4];
    const float* bo = (const float*)d_in[5];
    float* out = (float*)d_out;

    dim3 gq(D_ / 128, M_ / 128, 3);      // 8 x 32 x 3
    qkv_kernel<<<gq, 256>>>(x, Wq, Wk, Wv);

    dim3 ga(N_ / 128, B_ * H_);          // 16 x 32
    flash_kernel<<<ga, 128>>>();

    dim3 go(D_ / 128, M_ / 128);         // 8 x 32
    outproj_kernel<<<go, 256>>>(Wo, bo, out);
}

// round 12
// speedup vs baseline: 1.0008x; 1.0008x over previous
#include <cuda_runtime.h>

// Problem constants
#define B_  2
#define N_  2048
#define D_  1024
#define H_  16
#define DH  64
#define M_  (B_ * N_)   // 4096 rows

// Scratch (device globals — no allocation allowed)
__device__ float g_Q[M_ * D_];
__device__ float g_K[M_ * D_];
__device__ float g_V[M_ * D_];
__device__ float g_C[M_ * D_];

// ---------------------------------------------------------------------------
// Packed f32x2 helpers (Blackwell FFMA2 — 2 FMAs per fma-pipe instruction)
// ---------------------------------------------------------------------------
typedef unsigned long long u64;

__device__ __forceinline__ u64 pack2(float x, float y) {
    u64 r; asm("mov.b64 %0, {%1,%2};" : "=l"(r) : "f"(x), "f"(y)); return r;
}
__device__ __forceinline__ float2 unpack2(u64 v) {
    float2 r; asm("mov.b64 {%0,%1}, %2;" : "=f"(r.x), "=f"(r.y) : "l"(v)); return r;
}
__device__ __forceinline__ u64 ffma2(u64 a, u64 b, u64 c) {
    u64 d; asm("fma.rn.f32x2 %0, %1, %2, %3;" : "=l"(d) : "l"(a), "l"(b), "l"(c)); return d;
}
__device__ __forceinline__ u64 fmul2(u64 a, u64 b) {
    u64 d; asm("mul.rn.f32x2 %0, %1, %2;" : "=l"(d) : "l"(a), "l"(b)); return d;
}
__device__ __forceinline__ u64 swap2(u64 v) {   // {lo,hi} -> {hi,lo}
    u64 r;
    asm("{\n\t.reg .b32 lo, hi;\n\t"
        "mov.b64 {lo, hi}, %1;\n\t"
        "mov.b64 %0, {hi, lo};\n\t}"
        : "=l"(r) : "l"(v));
    return r;
}

// ---------------------------------------------------------------------------
// NT SGEMM tile, FFMA2 diagonal/anti-diagonal microkernel:
//   C[m][n] = sum_k A[m][k] * W[n][k] (+ bias[n])
// BM=BN=128, BK=8, 256 threads, 8x8 per thread as 4x4 PAIR blocks.
// For a-pair {a0,a1} and w-pair {w0,w1}:
//   accD += {a0,a1}*{w0,w1}  -> diag   (a0w0, a1w1)
//   accA += {a0,a1}*{w1,w0}  -> anti   (a0w1, a1w0)
// Operands come straight from 4 LDS.128 per k-step (no duplicated smem).
// ---------------------------------------------------------------------------
__device__ __forceinline__ void gemm_tile(const float* __restrict__ A,
                                          const float* __restrict__ W,
                                          float* __restrict__ C,
                                          const float* __restrict__ bias)
{
    __shared__ float As[8][128];
    __shared__ float Ws[8][128];

    const int tid = threadIdx.x;          // 0..255
    const int tx  = tid & 15;             // 0..15 (N direction)
    const int ty  = tid >> 4;             // 0..15 (M direction)
    const int mbase = blockIdx.y * 128;
    const int nbase = blockIdx.x * 128;

    // Global-load mapping: each thread loads one float4 per tile per matrix.
    const int lr = tid >> 1;              // row within 128-row tile
    const int lc = (tid & 1) * 4;         // 0 or 4 within the 8-wide K slab
    const float* Ap = A + (size_t)(mbase + lr) * D_ + lc;
    const float* Wp = W + (size_t)(nbase + lr) * D_ + lc;

    u64 accD[4][4], accA[4][4];
    #pragma unroll
    for (int i = 0; i < 4; i++)
        #pragma unroll
        for (int j = 0; j < 4; j++) { accD[i][j] = 0ull; accA[i][j] = 0ull; }

    float4 av = *(const float4*)(Ap);
    float4 wv = *(const float4*)(Wp);

    for (int kb = 0; kb < D_; kb += 8) {
        // store current slab (transposed: [k][row])
        As[lc + 0][lr] = av.x; As[lc + 1][lr] = av.y;
        As[lc + 2][lr] = av.z; As[lc + 3][lr] = av.w;
        Ws[lc + 0][lr] = wv.x; Ws[lc + 1][lr] = wv.y;
        Ws[lc + 2][lr] = wv.z; Ws[lc + 3][lr] = wv.w;
        __syncthreads();

        // prefetch next slab while computing
        if (kb + 8 < D_) {
            av = *(const float4*)(Ap + kb + 8);
            wv = *(const float4*)(Wp + kb + 8);
        }

        #pragma unroll
        for (int k = 0; k < 8; k++) {
            ulonglong2 aA = *(const ulonglong2*)&As[k][ty * 8];      // {a0,a1},{a2,a3}
            ulonglong2 aB = *(const ulonglong2*)&As[k][ty * 8 + 4];  // {a4,a5},{a6,a7}
            ulonglong2 wA = *(const ulonglong2*)&Ws[k][tx * 8];
            ulonglong2 wB = *(const ulonglong2*)&Ws[k][tx * 8 + 4];
            u64 a2[4] = { aA.x, aA.y, aB.x, aB.y };
            u64 w2[4] = { wA.x, wA.y, wB.x, wB.y };
            u64 ws[4];
            #pragma unroll
            for (int j = 0; j < 4; j++) ws[j] = swap2(w2[j]);

            #pragma unroll
            for (int i = 0; i < 4; i++)
                #pragma unroll
                for (int j = 0; j < 4; j++) {
                    accD[i][j] = ffma2(a2[i], w2[j], accD[i][j]);
                    accA[i][j] = ffma2(a2[i], ws[j], accA[i][j]);
                }
        }
        __syncthreads();
    }

    // Epilogue: unscramble diag/anti pairs into rows, add bias, store float4.
    #pragma unroll
    for (int ip = 0; ip < 4; ip++) {
        const size_t r0 = (size_t)(mbase + ty * 8 + 2 * ip) * D_;
        const size_t r1 = r0 + D_;
        #pragma unroll
        for (int jh = 0; jh < 2; jh++) {               // two float4 per row
            const int c = nbase + tx * 8 + jh * 4;
            float2 d0 = unpack2(accD[ip][2 * jh]);     // cols c, c+1 (diag)
            float2 x0 = unpack2(accA[ip][2 * jh]);     // cols c+1, c (anti)
            float2 d1 = unpack2(accD[ip][2 * jh + 1]); // cols c+2, c+3
            float2 x1 = unpack2(accA[ip][2 * jh + 1]);
            float4 row0 = make_float4(d0.x, x0.x, d1.x, x1.x);
            float4 row1 = make_float4(x0.y, d0.y, x1.y, d1.y);
            if (bias) {
                float4 bb = *(const float4*)(bias + c);
                row0.x += bb.x; row0.y += bb.y; row0.z += bb.z; row0.w += bb.w;
                row1.x += bb.x; row1.y += bb.y; row1.z += bb.z; row1.w += bb.w;
            }
            *(float4*)(C + r0 + c) = row0;
            *(float4*)(C + r1 + c) = row1;
        }
    }
}

// Fused QKV projection: blockIdx.z selects which weight/output (x tiles L2-shared).
__global__ void __launch_bounds__(256, 2) qkv_kernel(const float* __restrict__ x,
                                                     const float* __restrict__ Wq,
                                                     const float* __restrict__ Wk,
                                                     const float* __restrict__ Wv)
{
    const float* W;
    float* O;
    if (blockIdx.z == 0)      { W = Wq; O = g_Q; }
    else if (blockIdx.z == 1) { W = Wk; O = g_K; }
    else                      { W = Wv; O = g_V; }
    gemm_tile(x, W, O, nullptr);
}

// Output projection: out = ctx @ Wo^T + bo
__global__ void __launch_bounds__(256, 2) outproj_kernel(const float* __restrict__ Wo,
                                                         const float* __restrict__ bo,
                                                         float* __restrict__ out)
{
    gemm_tile(g_C, Wo, out, bo);
}

// ---------------------------------------------------------------------------
// Flash attention (fp32, FFMA2), double-buffered 16-row KV tiles.
// Grid: (N_/128, B_*H_). Block: 128 threads; each thread owns ONE query row:
//   q[64] and o[64] live in registers as 32 packed f32x2 each.
// ---------------------------------------------------------------------------
__global__ void __launch_bounds__(128) flash_kernel()
{
    __shared__ float Ks[2][16][64];
    __shared__ float Vs[2][16][64];

    const int bh = blockIdx.y;
    const int b  = bh >> 4;
    const int h  = bh & 15;
    const int n  = blockIdx.x * 128 + threadIdx.x;     // query row (always < 2048)
    const size_t row = (size_t)(b * N_ + n) * D_ + h * DH;

    // Load + pre-scale q into packed registers
    u64 q2[32];
    {
        const float sc = 0.125f;  // dh^-0.5 = 64^-0.5
        #pragma unroll
        for (int d4 = 0; d4 < 16; d4++) {
            float4 t = *(const float4*)(g_Q + row + d4 * 4);
            q2[2 * d4]     = pack2(t.x * sc, t.y * sc);
            q2[2 * d4 + 1] = pack2(t.z * sc, t.w * sc);
        }
    }

    u64 o2[32];
    #pragma unroll
    for (int i = 0; i < 32; i++) o2[i] = 0ull;   // bit pattern of (0.f, 0.f)
    float m = -1e30f;
    float l = 0.0f;

    const size_t kvbase = (size_t)b * N_ * D_ + h * DH;

    // Per-thread staging map: 2 float4 of K + 2 float4 of V per 16x64 tile.
    const int f0  = threadIdx.x;
    const int f1  = threadIdx.x + 128;
    const int jr0 = f0 >> 4, c40 = (f0 & 15) * 4;
    const int jr1 = f1 >> 4, c41 = (f1 & 15) * 4;
    const size_t off0 = (size_t)jr0 * D_ + c40;
    const size_t off1 = (size_t)jr1 * D_ + c41;

    float4 kr0, kr1, vr0, vr1;

    // Prologue: tile 0 into buffer 0.
    kr0 = *(const float4*)(g_K + kvbase + off0);
    kr1 = *(const float4*)(g_K + kvbase + off1);
    vr0 = *(const float4*)(g_V + kvbase + off0);
    vr1 = *(const float4*)(g_V + kvbase + off1);
    *(float4*)&Ks[0][jr0][c40] = kr0;
    *(float4*)&Ks[0][jr1][c41] = kr1;
    *(float4*)&Vs[0][jr0][c40] = vr0;
    *(float4*)&Vs[0][jr1][c41] = vr1;
    __syncthreads();

    const int T = N_ / 16;   // 128 tiles
    for (int t = 0; t < T; t++) {
        const int cur = t & 1;

        // Issue next tile's global loads; latency overlaps the compute below.
        if (t + 1 < T) {
            const size_t g = kvbase + (size_t)(t + 1) * 16 * D_;
            kr0 = *(const float4*)(g_K + g + off0);
            kr1 = *(const float4*)(g_K + g + off1);
            vr0 = *(const float4*)(g_V + g + off0);
            vr1 = *(const float4*)(g_V + g + off1);
        }

        // S = q . K_j (packed FFMA2, 4 independent accumulator chains)
        float s[16];
        float tmax = -1e30f;
        #pragma unroll
        for (int j = 0; j < 16; j++) {
            const ulonglong2* kp = (const ulonglong2*)&Ks[cur][j][0];  // LDS.128
            u64 a0 = 0ull, a1 = 0ull, a2 = 0ull, a3 = 0ull;
            #pragma unroll
            for (int e = 0; e < 16; e += 2) {
                ulonglong2 ka = kp[e];
                ulonglong2 kb = kp[e + 1];
                a0 = ffma2(q2[2 * e + 0], ka.x, a0);
                a1 = ffma2(q2[2 * e + 1], ka.y, a1);
                a2 = ffma2(q2[2 * e + 2], kb.x, a2);
                a3 = ffma2(q2[2 * e + 3], kb.y, a3);
            }
            float2 t0 = unpack2(a0), t1 = unpack2(a1);
            float2 t2 = unpack2(a2), t3 = unpack2(a3);
            s[j] = ((t0.x + t0.y) + (t1.x + t1.y)) + ((t2.x + t2.y) + (t3.x + t3.y));
            tmax = fmaxf(tmax, s[j]);
        }

        // Online softmax update
        const float mnew = fmaxf(m, tmax);
        const float corr = __expf(m - mnew);   // first iter: exp(-huge) = 0
        m = mnew;
        float ps = 0.0f;
        #pragma unroll
        for (int j = 0; j < 16; j++) { s[j] = __expf(s[j] - mnew); ps += s[j]; }
        l = l * corr + ps;

        const u64 c2 = pack2(corr, corr);
        #pragma unroll
        for (int i = 0; i < 32; i++) o2[i] = fmul2(o2[i], c2);

        // O += P . V (packed FFMA2)
        #pragma unroll
        for (int j = 0; j < 16; j++) {
            const u64 p2 = pack2(s[j], s[j]);
            const ulonglong2* vp = (const ulonglong2*)&Vs[cur][j][0];
            #pragma unroll
            for (int e = 0; e < 16; e++) {
                ulonglong2 vv = vp[e];
                o2[2 * e]     = ffma2(p2, vv.x, o2[2 * e]);
                o2[2 * e + 1] = ffma2(p2, vv.y, o2[2 * e + 1]);
            }
        }

        // Store prefetched tile into the other buffer; barrier covers both
        // "tile t fully consumed" and "tile t+1 visible".
        if (t + 1 < T) {
            const int nxt = 1 - cur;
            *(float4*)&Ks[nxt][jr0][c40] = kr0;
            *(float4*)&Ks[nxt][jr1][c41] = kr1;
            *(float4*)&Vs[nxt][jr0][c40] = vr0;
            *(float4*)&Vs[nxt][jr1][c41] = vr1;
        }
        __syncthreads();
    }

    // Normalize and write context (same [row, h*64 + d] layout as Q)
    const float inv = 1.0f / l;
    const u64 i2 = pack2(inv, inv);
    #pragma unroll
    for (int e = 0; e < 16; e++) {
        ulonglong2 w;
        w.x = fmul2(o2[2 * e],     i2);
        w.y = fmul2(o2[2 * e + 1], i2);
        *(ulonglong2*)(g_C + row + e * 4) = w;
    }
}

// ---------------------------------------------------------------------------
// Launch
// ---------------------------------------------------------------------------
extern "C" void kernel_launch(void* const* d_in, const int* in_sizes, int n_in,
                              void* d_out, int out_size)
{
    (void)in_sizes; (void)n_in; (void)out_size;
    const float* x  = (const float*)d_in[0];
    const float* Wq = (const float*)d_in[1];
    const float* Wk = (const float*)d_in[2];
    const float* Wv = (const float*)d_in[3];
    const float* Wo = (const float*)d_in[4];
    const float* bo = (const float*)d_in[5];
    float* out = (float*)d_out;

    dim3 gq(D_ / 128, M_ / 128, 3);      // 8 x 32 x 3
    qkv_kernel<<<gq, 256>>>(x, Wq, Wk, Wv);

    dim3 ga(N_ / 128, B_ * H_);          // 16 x 32
    flash_kernel<<<ga, 128>>>();

    dim3 go(D_ / 128, M_ / 128);         // 8 x 32
    outproj_kernel<<<go, 256>>>(Wo, bo, out);
}

// round 13
// speedup vs baseline: 1.0013x; 1.0005x over previous
#include <cuda_runtime.h>

// Problem constants
#define B_  2
#define N_  2048
#define D_  1024
#define H_  16
#define DH  64
#define M_  (B_ * N_)   // 4096 rows

// Scratch (device globals — no allocation allowed)
__device__ float g_Q[M_ * D_];
__device__ float g_K[M_ * D_];
__device__ float g_V[M_ * D_];
__device__ float g_C[M_ * D_];

// ---------------------------------------------------------------------------
// Packed f32x2 helpers (Blackwell FFMA2 — 2 FMAs per fma-pipe instruction)
// ---------------------------------------------------------------------------
typedef unsigned long long u64;

__device__ __forceinline__ u64 pack2(float x, float y) {
    u64 r; asm("mov.b64 %0, {%1,%2};" : "=l"(r) : "f"(x), "f"(y)); return r;
}
__device__ __forceinline__ float2 unpack2(u64 v) {
    float2 r; asm("mov.b64 {%0,%1}, %2;" : "=f"(r.x), "=f"(r.y) : "l"(v)); return r;
}
__device__ __forceinline__ u64 ffma2(u64 a, u64 b, u64 c) {
    u64 d; asm("fma.rn.f32x2 %0, %1, %2, %3;" : "=l"(d) : "l"(a), "l"(b), "l"(c)); return d;
}
__device__ __forceinline__ u64 fmul2(u64 a, u64 b) {
    u64 d; asm("mul.rn.f32x2 %0, %1, %2;" : "=l"(d) : "l"(a), "l"(b)); return d;
}
__device__ __forceinline__ u64 swap2(u64 v) {   // {lo,hi} -> {hi,lo}
    u64 r;
    asm("{\n\t.reg .b32 lo, hi;\n\t"
        "mov.b64 {lo, hi}, %1;\n\t"
        "mov.b64 %0, {hi, lo};\n\t}"
        : "=l"(r) : "l"(v));
    return r;
}

// ---------------------------------------------------------------------------
// NT SGEMM tile, FFMA2 diagonal/anti-diagonal microkernel:
//   C[m][n] = sum_k A[m][k] * W[n][k] (+ bias[n])
// BM=BN=128, BK=8, 256 threads, 8x8 per thread as 4x4 PAIR blocks.
// For a-pair {a0,a1} and w-pair {w0,w1}:
//   accD += {a0,a1}*{w0,w1}  -> diag   (a0w0, a1w1)
//   accA += {a0,a1}*{w1,w0}  -> anti   (a0w1, a1w0)
// Operands come straight from 4 LDS.128 per k-step (no duplicated smem).
// ---------------------------------------------------------------------------
__device__ __forceinline__ void gemm_tile(const float* __restrict__ A,
                                          const float* __restrict__ W,
                                          float* __restrict__ C,
                                          const float* __restrict__ bias)
{
    __shared__ float As[8][128];
    __shared__ float Ws[8][128];

    const int tid = threadIdx.x;          // 0..255
    const int tx  = tid & 15;             // 0..15 (N direction)
    const int ty  = tid >> 4;             // 0..15 (M direction)
    const int mbase = blockIdx.y * 128;
    const int nbase = blockIdx.x * 128;

    // Global-load mapping: each thread loads one float4 per tile per matrix.
    const int lr = tid >> 1;              // row within 128-row tile
    const int lc = (tid & 1) * 4;         // 0 or 4 within the 8-wide K slab
    const float* Ap = A + (size_t)(mbase + lr) * D_ + lc;
    const float* Wp = W + (size_t)(nbase + lr) * D_ + lc;

    u64 accD[4][4], accA[4][4];
    #pragma unroll
    for (int i = 0; i < 4; i++)
        #pragma unroll
        for (int j = 0; j < 4; j++) { accD[i][j] = 0ull; accA[i][j] = 0ull; }

    float4 av = *(const float4*)(Ap);
    float4 wv = *(const float4*)(Wp);

    for (int kb = 0; kb < D_; kb += 8) {
        // store current slab (transposed: [k][row])
        As[lc + 0][lr] = av.x; As[lc + 1][lr] = av.y;
        As[lc + 2][lr] = av.z; As[lc + 3][lr] = av.w;
        Ws[lc + 0][lr] = wv.x; Ws[lc + 1][lr] = wv.y;
        Ws[lc + 2][lr] = wv.z; Ws[lc + 3][lr] = wv.w;
        __syncthreads();

        // prefetch next slab while computing
        if (kb + 8 < D_) {
            av = *(const float4*)(Ap + kb + 8);
            wv = *(const float4*)(Wp + kb + 8);
        }

        #pragma unroll
        for (int k = 0; k < 8; k++) {
            ulonglong2 aA = *(const ulonglong2*)&As[k][ty * 8];      // {a0,a1},{a2,a3}
            ulonglong2 aB = *(const ulonglong2*)&As[k][ty * 8 + 4];  // {a4,a5},{a6,a7}
            ulonglong2 wA = *(const ulonglong2*)&Ws[k][tx * 8];
            ulonglong2 wB = *(const ulonglong2*)&Ws[k][tx * 8 + 4];
            u64 a2[4] = { aA.x, aA.y, aB.x, aB.y };
            u64 w2[4] = { wA.x, wA.y, wB.x, wB.y };
            u64 ws[4];
            #pragma unroll
            for (int j = 0; j < 4; j++) ws[j] = swap2(w2[j]);

            #pragma unroll
            for (int i = 0; i < 4; i++)
                #pragma unroll
                for (int j = 0; j < 4; j++) {
                    accD[i][j] = ffma2(a2[i], w2[j], accD[i][j]);
                    accA[i][j] = ffma2(a2[i], ws[j], accA[i][j]);
                }
        }
        __syncthreads();
    }

    // Epilogue: unscramble diag/anti pairs into rows, add bias, store float4.
    #pragma unroll
    for (int ip = 0; ip < 4; ip++) {
        const size_t r0 = (size_t)(mbase + ty * 8 + 2 * ip) * D_;
        const size_t r1 = r0 + D_;
        #pragma unroll
        for (int jh = 0; jh < 2; jh++) {               // two float4 per row
            const int c = nbase + tx * 8 + jh * 4;
            float2 d0 = unpack2(accD[ip][2 * jh]);     // cols c, c+1 (diag)
            float2 x0 = unpack2(accA[ip][2 * jh]);     // cols c+1, c (anti)
            float2 d1 = unpack2(accD[ip][2 * jh + 1]); // cols c+2, c+3
            float2 x1 = unpack2(accA[ip][2 * jh + 1]);
            float4 row0 = make_float4(d0.x, x0.x, d1.x, x1.x);
            float4 row1 = make_float4(x0.y, d0.y, x1.y, d1.y);
            if (bias) {
                float4 bb = *(const float4*)(bias + c);
                row0.x += bb.x; row0.y += bb.y; row0.z += bb.z; row0.w += bb.w;
                row1.x += bb.x; row1.y += bb.y; row1.z += bb.z; row1.w += bb.w;
            }
            *(float4*)(C + r0 + c) = row0;
            *(float4*)(C + r1 + c) = row1;
        }
    }
}

// Fused QKV projection: blockIdx.z selects which weight/output (x tiles L2-shared).
__global__ void __launch_bounds__(256, 2) qkv_kernel(const float* __restrict__ x,
                                                     const float* __restrict__ Wq,
                                                     const float* __restrict__ Wk,
                                                     const float* __restrict__ Wv)
{
    const float* W;
    float* O;
    if (blockIdx.z == 0)      { W = Wq; O = g_Q; }
    else if (blockIdx.z == 1) { W = Wk; O = g_K; }
    else                      { W = Wv; O = g_V; }
    gemm_tile(x, W, O, nullptr);
}

// Output projection: out = ctx @ Wo^T + bo
__global__ void __launch_bounds__(256, 2) outproj_kernel(const float* __restrict__ Wo,
                                                         const float* __restrict__ bo,
                                                         float* __restrict__ out)
{
    gemm_tile(g_C, Wo, out, bo);
}

// ---------------------------------------------------------------------------
// Flash attention (fp32, FFMA2), double-buffered 16-row KV tiles.
// Grid: (N_/128, B_*H_). Block: 128 threads; each thread owns ONE query row:
//   q[64] and o[64] live in registers as 32 packed f32x2 each.
// ---------------------------------------------------------------------------
__global__ void __launch_bounds__(128) flash_kernel()
{
    __shared__ float Ks[2][16][64];
    __shared__ float Vs[2][16][64];

    const int bh = blockIdx.y;
    const int b  = bh >> 4;
    const int h  = bh & 15;
    const int n  = blockIdx.x * 128 + threadIdx.x;     // query row (always < 2048)
    const size_t row = (size_t)(b * N_ + n) * D_ + h * DH;

    // Load + pre-scale q into packed registers
    u64 q2[32];
    {
        const float sc = 0.125f;  // dh^-0.5 = 64^-0.5
        #pragma unroll
        for (int d4 = 0; d4 < 16; d4++) {
            float4 t = *(const float4*)(g_Q + row + d4 * 4);
            q2[2 * d4]     = pack2(t.x * sc, t.y * sc);
            q2[2 * d4 + 1] = pack2(t.z * sc, t.w * sc);
        }
    }

    u64 o2[32];
    #pragma unroll
    for (int i = 0; i < 32; i++) o2[i] = 0ull;   // bit pattern of (0.f, 0.f)
    float m = -1e30f;
    float l = 0.0f;

    const size_t kvbase = (size_t)b * N_ * D_ + h * DH;

    // Per-thread staging map: 2 float4 of K + 2 float4 of V per 16x64 tile.
    const int f0  = threadIdx.x;
    const int f1  = threadIdx.x + 128;
    const int jr0 = f0 >> 4, c40 = (f0 & 15) * 4;
    const int jr1 = f1 >> 4, c41 = (f1 & 15) * 4;
    const size_t off0 = (size_t)jr0 * D_ + c40;
    const size_t off1 = (size_t)jr1 * D_ + c41;

    float4 kr0, kr1, vr0, vr1;

    // Prologue: tile 0 into buffer 0.
    kr0 = *(const float4*)(g_K + kvbase + off0);
    kr1 = *(const float4*)(g_K + kvbase + off1);
    vr0 = *(const float4*)(g_V + kvbase + off0);
    vr1 = *(const float4*)(g_V + kvbase + off1);
    *(float4*)&Ks[0][jr0][c40] = kr0;
    *(float4*)&Ks[0][jr1][c41] = kr1;
    *(float4*)&Vs[0][jr0][c40] = vr0;
    *(float4*)&Vs[0][jr1][c41] = vr1;
    __syncthreads();

    const int T = N_ / 16;   // 128 tiles
    for (int t = 0; t < T; t++) {
        const int cur = t & 1;

        // Issue next tile's global loads; latency overlaps the compute below.
        if (t + 1 < T) {
            const size_t g = kvbase + (size_t)(t + 1) * 16 * D_;
            kr0 = *(const float4*)(g_K + g + off0);
            kr1 = *(const float4*)(g_K + g + off1);
            vr0 = *(const float4*)(g_V + g + off0);
            vr1 = *(const float4*)(g_V + g + off1);
        }

        // S = q . K_j (packed FFMA2, 4 independent accumulator chains)
        float s[16];
        float tmax = -1e30f;
        #pragma unroll
        for (int j = 0; j < 16; j++) {
            const ulonglong2* kp = (const ulonglong2*)&Ks[cur][j][0];  // LDS.128
            u64 a0 = 0ull, a1 = 0ull, a2 = 0ull, a3 = 0ull;
            #pragma unroll
            for (int e = 0; e < 16; e += 2) {
                ulonglong2 ka = kp[e];
                ulonglong2 kb = kp[e + 1];
                a0 = ffma2(q2[2 * e + 0], ka.x, a0);
                a1 = ffma2(q2[2 * e + 1], ka.y, a1);
                a2 = ffma2(q2[2 * e + 2], kb.x, a2);
                a3 = ffma2(q2[2 * e + 3], kb.y, a3);
            }
            float2 t0 = unpack2(a0), t1 = unpack2(a1);
            float2 t2 = unpack2(a2), t3 = unpack2(a3);
            s[j] = ((t0.x + t0.y) + (t1.x + t1.y)) + ((t2.x + t2.y) + (t3.x + t3.y));
            tmax = fmaxf(tmax, s[j]);
        }

        // Online softmax update
        const float mnew = fmaxf(m, tmax);
        const float corr = __expf(m - mnew);   // first iter: exp(-huge) = 0
        m = mnew;
        float ps = 0.0f;
        #pragma unroll
        for (int j = 0; j < 16; j++) { s[j] = __expf(s[j] - mnew); ps += s[j]; }
        l = l * corr + ps;

        const u64 c2 = pack2(corr, corr);
        #pragma unroll
        for (int i = 0; i < 32; i++) o2[i] = fmul2(o2[i], c2);

        // O += P . V (packed FFMA2)
        #pragma unroll
        for (int j = 0; j < 16; j++) {
            const u64 p2 = pack2(s[j], s[j]);
            const ulonglong2* vp = (const ulonglong2*)&Vs[cur][j][0];
            #pragma unroll
            for (int e = 0; e < 16; e++) {
                ulonglong2 vv = vp[e];
                o2[2 * e]     = ffma2(p2, vv.x, o2[2 * e]);
                o2[2 * e + 1] = ffma2(p2, vv.y, o2[2 * e + 1]);
            }
        }

        // Store prefetched tile into the other buffer; barrier covers both
        // "tile t fully consumed" and "tile t+1 visible".
        if (t + 1 < T) {
            const int nxt = 1 - cur;
            *(float4*)&Ks[nxt][jr0][c40] = kr0;
            *(float4*)&Ks[nxt][jr1][c41] = kr1;
            *(float4*)&Vs[nxt][jr0][c40] = vr0;
            *(float4*)&Vs[nxt][jr1][c41] = vr1;
        }
        __syncthreads();
    }

    // Normalize and write context (same [row, h*64 + d] layout as Q)
    const float inv = 1.0f / l;
    const u64 i2 = pack2(inv, inv);
    #pragma unroll
    for (int e = 0; e < 16; e++) {
        ulonglong2 w;
        w.x = fmul2(o2[2 * e],     i2);
        w.y = fmul2(o2[2 * e + 1], i2);
        *(ulonglong2*)(g_C + row + e * 4) = w;
    }
}

// ---------------------------------------------------------------------------
// Launch
// ---------------------------------------------------------------------------
extern "C" void kernel_launch(void* const* d_in, const int* in_sizes, int n_in,
                              void* d_out, int out_size)
{
    (void)in_sizes; (void)n_in; (void)out_size;
    const float* x  = (const float*)d_in[0];
    const float* Wq = (const float*)d_in[1];
    const float* Wk = (const float*)d_in[2];
    const float* Wv = (const float*)d_in[3];
    const float* Wo = (const float*)d_in[4];
    const float* bo = (const float*)d_in[5];
    float* out = (float*)d_out;

    dim3 gq(D_ / 128, M_ / 128, 3);      // 8 x 32 x 3
    qkv_kernel<<<gq, 256>>>(x, Wq, Wk, Wv);

    dim3 ga(N_ / 128, B_ * H_);          // 16 x 32
    flash_kernel<<<ga, 128>>>();

    dim3 go(D_ / 128, M_ / 128);         // 8 x 32
    outproj_kernel<<<go, 256>>>(Wo, bo, out);
}